// round 16
// baseline (speedup 1.0000x reference)
#include <cuda_runtime.h>
#include <math.h>

// Problem constants (shapes fixed by the dataset; runtime dims derived from in_sizes)
#define MAXN 100000
#define DIM  64

// Scratch (allocation-free rule: __device__ globals)
__device__ __align__(16) float g_hneigh[MAXN * DIM];
__device__ __align__(16) float g_h2[MAXN * DIM];
__device__ __align__(16) float g_gate[MAXN];

// ---------------------------------------------------------------------------
// zero h_neigh
// ---------------------------------------------------------------------------
__global__ void zero_kernel(int n4) {
    int i = blockIdx.x * blockDim.x + threadIdx.x;
    if (i < n4) ((float4*)g_hneigh)[i] = make_float4(0.f, 0.f, 0.f, 0.f);
}

// ---------------------------------------------------------------------------
// Edge kernel: per block, 128 edges.
//   A[128][128] = [h_src | h_dst]  (smem, gathered)
//   hid = relu(A @ We1 + be1)      (128x64, K=128)
//   m   = hid @ We2 + be2          (128x64, K=64)
//   atomicAdd(h_neigh[dst], h_src * m)
// 256 threads, 8x4 register frags per thread.
// dyn smem: A 64KB + W1 32KB + W2 16KB + Hid 32KB = 144KB
// ---------------------------------------------------------------------------
__global__ __launch_bounds__(256, 1) void edge_kernel(
    const float* __restrict__ x,
    const float* __restrict__ We1, const float* __restrict__ be1,
    const float* __restrict__ We2, const float* __restrict__ be2,
    const int* __restrict__ src, const int* __restrict__ dst,
    int E)
{
    extern __shared__ float smem[];
    float* A   = smem;                    // [128][128]
    float* W1  = A  + 128 * 128;          // [128][64]
    float* W2  = W1 + 128 * 64;           // [64][64]
    float* Hid = W2 + 64 * 64;            // [128][64]
    __shared__ int   s_src[128];
    __shared__ int   s_dst[128];
    __shared__ float s_b1[64];
    __shared__ float s_b2[64];

    const int tid  = threadIdx.x;
    const int lane = tid & 31;
    const int w    = tid >> 5;
    const int e0   = blockIdx.x * 128;

    // weights + biases into smem
    for (int i = tid; i < 128 * 64 / 4; i += 256)
        ((float4*)W1)[i] = ((const float4*)We1)[i];
    for (int i = tid; i < 64 * 64 / 4; i += 256)
        ((float4*)W2)[i] = ((const float4*)We2)[i];
    if (tid < 64)  s_b1[tid] = be1[tid];
    else if (tid < 128) s_b2[tid - 64] = be2[tid - 64];

    // edge indices
    if (tid < 128) {
        int e = e0 + tid;
        s_src[tid] = (e < E) ? src[e] : 0;
    } else {
        int t2 = tid - 128;
        int e  = e0 + t2;
        s_dst[t2] = (e < E) ? dst[e] : -1;
    }
    __syncthreads();

    // gather: warp per row per pass (coalesced global, conflict-free smem)
    // lane 0..15 -> src half, lane 16..31 -> dst half
    for (int r = w; r < 128; r += 8) {
        int idx = (lane < 16) ? s_src[r] : s_dst[r];
        if (idx < 0) idx = 0;
        float4 v = ((const float4*)(x + (size_t)idx * DIM))[lane & 15];
        ((float4*)(A + r * 128))[lane] = v;
    }
    __syncthreads();

    // stage 1: hid = relu(A @ W1 + b1)
    const int tc = tid & 15;   // N-tile: cols tc*4 .. tc*4+3
    const int tr = tid >> 4;   // M-tile: rows tr*8 .. tr*8+7
    const float* Abase = A + tr * 8 * 128;

    float acc[8][4];
    {
        float b0 = s_b1[tc * 4 + 0], b1v = s_b1[tc * 4 + 1];
        float b2v = s_b1[tc * 4 + 2], b3 = s_b1[tc * 4 + 3];
        #pragma unroll
        for (int i = 0; i < 8; i++) {
            acc[i][0] = b0; acc[i][1] = b1v; acc[i][2] = b2v; acc[i][3] = b3;
        }
    }
    #pragma unroll 4
    for (int k = 0; k < 128; k++) {
        float4 wv = *(const float4*)(W1 + k * 64 + tc * 4);
        float a[8];
        #pragma unroll
        for (int i = 0; i < 8; i++) a[i] = Abase[i * 128 + k];
        #pragma unroll
        for (int i = 0; i < 8; i++) {
            acc[i][0] = fmaf(a[i], wv.x, acc[i][0]);
            acc[i][1] = fmaf(a[i], wv.y, acc[i][1]);
            acc[i][2] = fmaf(a[i], wv.z, acc[i][2]);
            acc[i][3] = fmaf(a[i], wv.w, acc[i][3]);
        }
    }
    #pragma unroll
    for (int i = 0; i < 8; i++) {
        float4 hv;
        hv.x = fmaxf(acc[i][0], 0.f); hv.y = fmaxf(acc[i][1], 0.f);
        hv.z = fmaxf(acc[i][2], 0.f); hv.w = fmaxf(acc[i][3], 0.f);
        *(float4*)(Hid + (tr * 8 + i) * 64 + tc * 4) = hv;
    }
    __syncthreads();

    // stage 2: m = hid @ W2 + b2
    float acc2[8][4];
    {
        float b0 = s_b2[tc * 4 + 0], b1v = s_b2[tc * 4 + 1];
        float b2v = s_b2[tc * 4 + 2], b3 = s_b2[tc * 4 + 3];
        #pragma unroll
        for (int i = 0; i < 8; i++) {
            acc2[i][0] = b0; acc2[i][1] = b1v; acc2[i][2] = b2v; acc2[i][3] = b3;
        }
    }
    const float* Hbase = Hid + tr * 8 * 64;
    #pragma unroll 4
    for (int k = 0; k < 64; k++) {
        float4 wv = *(const float4*)(W2 + k * 64 + tc * 4);
        float h[8];
        #pragma unroll
        for (int i = 0; i < 8; i++) h[i] = Hbase[i * 64 + k];
        #pragma unroll
        for (int i = 0; i < 8; i++) {
            acc2[i][0] = fmaf(h[i], wv.x, acc2[i][0]);
            acc2[i][1] = fmaf(h[i], wv.y, acc2[i][1]);
            acc2[i][2] = fmaf(h[i], wv.z, acc2[i][2]);
            acc2[i][3] = fmaf(h[i], wv.w, acc2[i][3]);
        }
    }

    // epilogue: atomicAdd(h_neigh[dst], h_src * m)
    #pragma unroll
    for (int i = 0; i < 8; i++) {
        int r = tr * 8 + i;
        int d = s_dst[r];
        if (d >= 0) {
            float* hn = g_hneigh + (size_t)d * DIM + tc * 4;
            const float* hs = A + r * 128 + tc * 4;  // h_src slice
            atomicAdd(hn + 0, hs[0] * acc2[i][0]);
            atomicAdd(hn + 1, hs[1] * acc2[i][1]);
            atomicAdd(hn + 2, hs[2] * acc2[i][2]);
            atomicAdd(hn + 3, hs[3] * acc2[i][3]);
        }
    }
}

// ---------------------------------------------------------------------------
// Node kernel: h2 = relu(h_neigh @ Wn + bn), gate = h2 @ Wg + bg
// per block 128 nodes; dyn smem: A 32KB + W 16KB + H 32KB = 80KB
// ---------------------------------------------------------------------------
__global__ __launch_bounds__(256) void node_kernel(
    const float* __restrict__ Wn, const float* __restrict__ bn,
    const float* __restrict__ Wg, const float* __restrict__ bg,
    int N)
{
    extern __shared__ float smem[];
    float* A = smem;             // [128][64]
    float* W = A + 128 * 64;     // [64][64]
    float* H = W + 64 * 64;      // [128][64]
    __shared__ float s_bn[64], s_wg[64];
    __shared__ float s_bg;

    const int tid = threadIdx.x;
    const int n0  = blockIdx.x * 128;

    for (int i = tid; i < 64 * 64 / 4; i += 256)
        ((float4*)W)[i] = ((const float4*)Wn)[i];
    if (tid < 64) { s_bn[tid] = bn[tid]; s_wg[tid] = Wg[tid]; }
    if (tid == 0) s_bg = bg[0];

    // gather (contiguous rows)
    {
        int r = tid >> 4;       // 0..15
        int c = tid & 15;
        for (int rr = r; rr < 128; rr += 16) {
            int n = n0 + rr;
            float4 v = (n < N) ? ((const float4*)(g_hneigh + (size_t)n * DIM))[c]
                               : make_float4(0.f, 0.f, 0.f, 0.f);
            ((float4*)(A + rr * 64))[c] = v;
        }
    }
    __syncthreads();

    const int tc = tid & 15;
    const int tr = tid >> 4;
    const float* Abase = A + tr * 8 * 64;

    float acc[8][4];
    {
        float b0 = s_bn[tc * 4 + 0], b1v = s_bn[tc * 4 + 1];
        float b2v = s_bn[tc * 4 + 2], b3 = s_bn[tc * 4 + 3];
        #pragma unroll
        for (int i = 0; i < 8; i++) {
            acc[i][0] = b0; acc[i][1] = b1v; acc[i][2] = b2v; acc[i][3] = b3;
        }
    }
    #pragma unroll 4
    for (int k = 0; k < 64; k++) {
        float4 wv = *(const float4*)(W + k * 64 + tc * 4);
        float a[8];
        #pragma unroll
        for (int i = 0; i < 8; i++) a[i] = Abase[i * 64 + k];
        #pragma unroll
        for (int i = 0; i < 8; i++) {
            acc[i][0] = fmaf(a[i], wv.x, acc[i][0]);
            acc[i][1] = fmaf(a[i], wv.y, acc[i][1]);
            acc[i][2] = fmaf(a[i], wv.z, acc[i][2]);
            acc[i][3] = fmaf(a[i], wv.w, acc[i][3]);
        }
    }
    #pragma unroll
    for (int i = 0; i < 8; i++) {
        int r = tr * 8 + i;
        int n = n0 + r;
        float4 hv;
        hv.x = fmaxf(acc[i][0], 0.f); hv.y = fmaxf(acc[i][1], 0.f);
        hv.z = fmaxf(acc[i][2], 0.f); hv.w = fmaxf(acc[i][3], 0.f);
        *(float4*)(H + r * 64 + tc * 4) = hv;
        if (n < N) *(float4*)(g_h2 + (size_t)n * DIM + tc * 4) = hv;
    }
    __syncthreads();

    // gate (rotated index -> conflict-free)
    if (tid < 128) {
        int n = n0 + tid;
        if (n < N) {
            const float* hr = H + tid * 64;
            float gacc = s_bg;
            #pragma unroll
            for (int j = 0; j < 64; j++) {
                int jj = (j + tid) & 63;
                gacc = fmaf(hr[jj], s_wg[jj], gacc);
            }
            g_gate[n] = gacc;
        }
    }
}

// ---------------------------------------------------------------------------
// Pool kernel: one block per graph (graph_ids sorted).
// segment max -> exp-weighted sums -> classifier
// ---------------------------------------------------------------------------
__global__ __launch_bounds__(256) void pool_kernel(
    const int* __restrict__ gid,
    const float* __restrict__ Wfc, const float* __restrict__ bfc,
    float* __restrict__ out, int N, int C)
{
    const int g   = blockIdx.x;
    const int tid = threadIdx.x;
    const int lane = tid & 31;
    const int w    = tid >> 5;

    // lower_bound for g and g+1
    int start, end;
    {
        int lo = 0, hi = N;
        while (lo < hi) { int mid = (lo + hi) >> 1; if (gid[mid] < g) lo = mid + 1; else hi = mid; }
        start = lo;
        lo = start; hi = N;
        while (lo < hi) { int mid = (lo + hi) >> 1; if (gid[mid] < g + 1) lo = mid + 1; else hi = mid; }
        end = lo;
    }

    __shared__ float s_red[8 * 64];
    __shared__ float s_scalar[8];
    __shared__ float s_gmax;
    __shared__ float s_pool[64];
    __shared__ float s_denom;

    // pass 1: segment max of gate
    float lmax = -3.4e38f;
    for (int n = start + tid; n < end; n += 256) lmax = fmaxf(lmax, g_gate[n]);
    #pragma unroll
    for (int o = 16; o > 0; o >>= 1) lmax = fmaxf(lmax, __shfl_xor_sync(0xFFFFFFFFu, lmax, o));
    if (lane == 0) s_scalar[w] = lmax;
    __syncthreads();
    if (tid == 0) {
        float m = s_scalar[0];
        #pragma unroll
        for (int i = 1; i < 8; i++) m = fmaxf(m, s_scalar[i]);
        s_gmax = m;
    }
    __syncthreads();
    const float gmax = s_gmax;

    // pass 2: denom + weighted feature sum (warp handles whole rows)
    float p0 = 0.f, p1 = 0.f, ds = 0.f;
    for (int n = start + w; n < end; n += 8) {
        float a = __expf(g_gate[n] - gmax);
        const float* hr = g_h2 + (size_t)n * DIM;
        p0 = fmaf(a, hr[lane],      p0);
        p1 = fmaf(a, hr[lane + 32], p1);
        ds += a;
    }
    s_red[w * 64 + lane]      = p0;
    s_red[w * 64 + lane + 32] = p1;
    if (lane == 0) s_scalar[w] = ds;
    __syncthreads();
    if (tid < 64) {
        float s = 0.f;
        #pragma unroll
        for (int i = 0; i < 8; i++) s += s_red[i * 64 + tid];
        s_pool[tid] = s;
    }
    if (tid == 0) {
        float d = 0.f;
        #pragma unroll
        for (int i = 0; i < 8; i++) d += s_scalar[i];
        s_denom = d;
    }
    __syncthreads();

    // classifier: out[g][c] = (pooled/denom) @ Wfc + bfc
    if (tid < C) {
        float o;
        if (end > start) {
            float inv = 1.0f / s_denom;
            float acc = 0.f;
            for (int j = 0; j < 64; j++)
                acc = fmaf(s_pool[j], Wfc[j * C + tid], acc);
            o = fmaf(acc, inv, bfc[tid]);
        } else {
            o = bfc[tid];
        }
        out[g * C + tid] = o;
    }
}

// ---------------------------------------------------------------------------
// launch
// ---------------------------------------------------------------------------
extern "C" void kernel_launch(void* const* d_in, const int* in_sizes, int n_in,
                              void* d_out, int out_size) {
    const float* x   = (const float*)d_in[0];
    const float* We1 = (const float*)d_in[1];
    const float* be1 = (const float*)d_in[2];
    const float* We2 = (const float*)d_in[3];
    const float* be2 = (const float*)d_in[4];
    const float* Wn  = (const float*)d_in[5];
    const float* bn  = (const float*)d_in[6];
    const float* Wg  = (const float*)d_in[7];
    const float* bg  = (const float*)d_in[8];
    const float* Wfc = (const float*)d_in[9];
    const float* bfc = (const float*)d_in[10];
    const int*   src = (const int*)d_in[11];
    const int*   dst = (const int*)d_in[12];
    const int*   gid = (const int*)d_in[13];
    float* out = (float*)d_out;

    const int N = in_sizes[0] / DIM;
    const int E = in_sizes[11];
    const int C = in_sizes[9] / DIM;   // 10
    const int G = out_size / C;        // 128

    const int SMEM_EDGE = (128 * 128 + 128 * 64 + 64 * 64 + 128 * 64) * 4;  // 144 KB
    const int SMEM_NODE = (128 * 64 + 64 * 64 + 128 * 64) * 4;              // 80 KB
    cudaFuncSetAttribute(edge_kernel, cudaFuncAttributeMaxDynamicSharedMemorySize, SMEM_EDGE);
    cudaFuncSetAttribute(node_kernel, cudaFuncAttributeMaxDynamicSharedMemorySize, SMEM_NODE);

    int n4 = N * DIM / 4;
    zero_kernel<<<(n4 + 255) / 256, 256>>>(n4);

    edge_kernel<<<(E + 127) / 128, 256, SMEM_EDGE>>>(x, We1, be1, We2, be2, src, dst, E);

    node_kernel<<<(N + 127) / 128, 256, SMEM_NODE>>>(Wn, bn, Wg, bg, N);

    pool_kernel<<<G, 256>>>(gid, Wfc, bfc, out, N, C);
}

// round 17
// speedup vs baseline: 1.0012x; 1.0012x over previous
#include <cuda_runtime.h>
#include <math.h>

// Problem constants (shapes fixed by the dataset; runtime dims derived from in_sizes)
#define MAXN 100000
#define DIM  64

// Scratch (allocation-free rule: __device__ globals)
__device__ __align__(16) float g_hneigh[MAXN * DIM];
__device__ __align__(16) float g_h2[MAXN * DIM];
__device__ __align__(16) float g_gate[MAXN];

// ---------------------------------------------------------------------------
// zero h_neigh
// ---------------------------------------------------------------------------
__global__ void zero_kernel(int n4) {
    int i = blockIdx.x * blockDim.x + threadIdx.x;
    if (i < n4) ((float4*)g_hneigh)[i] = make_float4(0.f, 0.f, 0.f, 0.f);
}

// ---------------------------------------------------------------------------
// Edge kernel: per block, 128 edges.
//   A[128][128] = [h_src | h_dst]  (smem, gathered)
//   hid = relu(A @ We1 + be1)      (128x64, K=128)
//   m   = hid @ We2 + be2          (128x64, K=64)
//   atomicAdd(h_neigh[dst], h_src * m)
// 256 threads, 8x4 register frags per thread.
// dyn smem: A 64KB + W1 32KB + W2 16KB + Hid 32KB = 144KB
// ---------------------------------------------------------------------------
__global__ __launch_bounds__(256, 1) void edge_kernel(
    const float* __restrict__ x,
    const float* __restrict__ We1, const float* __restrict__ be1,
    const float* __restrict__ We2, const float* __restrict__ be2,
    const int* __restrict__ src, const int* __restrict__ dst,
    int E)
{
    extern __shared__ float smem[];
    float* A   = smem;                    // [128][128]
    float* W1  = A  + 128 * 128;          // [128][64]
    float* W2  = W1 + 128 * 64;           // [64][64]
    float* Hid = W2 + 64 * 64;            // [128][64]
    __shared__ int   s_src[128];
    __shared__ int   s_dst[128];
    __shared__ float s_b1[64];
    __shared__ float s_b2[64];

    const int tid  = threadIdx.x;
    const int lane = tid & 31;
    const int w    = tid >> 5;
    const int e0   = blockIdx.x * 128;

    // weights + biases into smem
    for (int i = tid; i < 128 * 64 / 4; i += 256)
        ((float4*)W1)[i] = ((const float4*)We1)[i];
    for (int i = tid; i < 64 * 64 / 4; i += 256)
        ((float4*)W2)[i] = ((const float4*)We2)[i];
    if (tid < 64)  s_b1[tid] = be1[tid];
    else if (tid < 128) s_b2[tid - 64] = be2[tid - 64];

    // edge indices
    if (tid < 128) {
        int e = e0 + tid;
        s_src[tid] = (e < E) ? src[e] : 0;
    } else {
        int t2 = tid - 128;
        int e  = e0 + t2;
        s_dst[t2] = (e < E) ? dst[e] : -1;
    }
    __syncthreads();

    // gather: warp per row per pass (coalesced global, conflict-free smem)
    // lane 0..15 -> src half, lane 16..31 -> dst half
    for (int r = w; r < 128; r += 8) {
        int idx = (lane < 16) ? s_src[r] : s_dst[r];
        if (idx < 0) idx = 0;
        float4 v = ((const float4*)(x + (size_t)idx * DIM))[lane & 15];
        ((float4*)(A + r * 128))[lane] = v;
    }
    __syncthreads();

    // stage 1: hid = relu(A @ W1 + b1)
    const int tc = tid & 15;   // N-tile: cols tc*4 .. tc*4+3
    const int tr = tid >> 4;   // M-tile: rows tr*8 .. tr*8+7
    const float* Abase = A + tr * 8 * 128;

    float acc[8][4];
    {
        float b0 = s_b1[tc * 4 + 0], b1v = s_b1[tc * 4 + 1];
        float b2v = s_b1[tc * 4 + 2], b3 = s_b1[tc * 4 + 3];
        #pragma unroll
        for (int i = 0; i < 8; i++) {
            acc[i][0] = b0; acc[i][1] = b1v; acc[i][2] = b2v; acc[i][3] = b3;
        }
    }
    #pragma unroll 4
    for (int k = 0; k < 128; k++) {
        float4 wv = *(const float4*)(W1 + k * 64 + tc * 4);
        float a[8];
        #pragma unroll
        for (int i = 0; i < 8; i++) a[i] = Abase[i * 128 + k];
        #pragma unroll
        for (int i = 0; i < 8; i++) {
            acc[i][0] = fmaf(a[i], wv.x, acc[i][0]);
            acc[i][1] = fmaf(a[i], wv.y, acc[i][1]);
            acc[i][2] = fmaf(a[i], wv.z, acc[i][2]);
            acc[i][3] = fmaf(a[i], wv.w, acc[i][3]);
        }
    }
    #pragma unroll
    for (int i = 0; i < 8; i++) {
        float4 hv;
        hv.x = fmaxf(acc[i][0], 0.f); hv.y = fmaxf(acc[i][1], 0.f);
        hv.z = fmaxf(acc[i][2], 0.f); hv.w = fmaxf(acc[i][3], 0.f);
        *(float4*)(Hid + (tr * 8 + i) * 64 + tc * 4) = hv;
    }
    __syncthreads();

    // stage 2: m = hid @ W2 + b2
    float acc2[8][4];
    {
        float b0 = s_b2[tc * 4 + 0], b1v = s_b2[tc * 4 + 1];
        float b2v = s_b2[tc * 4 + 2], b3 = s_b2[tc * 4 + 3];
        #pragma unroll
        for (int i = 0; i < 8; i++) {
            acc2[i][0] = b0; acc2[i][1] = b1v; acc2[i][2] = b2v; acc2[i][3] = b3;
        }
    }
    const float* Hbase = Hid + tr * 8 * 64;
    #pragma unroll 4
    for (int k = 0; k < 64; k++) {
        float4 wv = *(const float4*)(W2 + k * 64 + tc * 4);
        float h[8];
        #pragma unroll
        for (int i = 0; i < 8; i++) h[i] = Hbase[i * 64 + k];
        #pragma unroll
        for (int i = 0; i < 8; i++) {
            acc2[i][0] = fmaf(h[i], wv.x, acc2[i][0]);
            acc2[i][1] = fmaf(h[i], wv.y, acc2[i][1]);
            acc2[i][2] = fmaf(h[i], wv.z, acc2[i][2]);
            acc2[i][3] = fmaf(h[i], wv.w, acc2[i][3]);
        }
    }

    // epilogue: atomicAdd(h_neigh[dst], h_src * m)
    #pragma unroll
    for (int i = 0; i < 8; i++) {
        int r = tr * 8 + i;
        int d = s_dst[r];
        if (d >= 0) {
            float* hn = g_hneigh + (size_t)d * DIM + tc * 4;
            const float* hs = A + r * 128 + tc * 4;  // h_src slice
            atomicAdd(hn + 0, hs[0] * acc2[i][0]);
            atomicAdd(hn + 1, hs[1] * acc2[i][1]);
            atomicAdd(hn + 2, hs[2] * acc2[i][2]);
            atomicAdd(hn + 3, hs[3] * acc2[i][3]);
        }
    }
}

// ---------------------------------------------------------------------------
// Node kernel: h2 = relu(h_neigh @ Wn + bn), gate = h2 @ Wg + bg
// per block 128 nodes; dyn smem: A 32KB + W 16KB + H 32KB = 80KB
// ---------------------------------------------------------------------------
__global__ __launch_bounds__(256) void node_kernel(
    const float* __restrict__ Wn, const float* __restrict__ bn,
    const float* __restrict__ Wg, const float* __restrict__ bg,
    int N)
{
    extern __shared__ float smem[];
    float* A = smem;             // [128][64]
    float* W = A + 128 * 64;     // [64][64]
    float* H = W + 64 * 64;      // [128][64]
    __shared__ float s_bn[64], s_wg[64];
    __shared__ float s_bg;

    const int tid = threadIdx.x;
    const int n0  = blockIdx.x * 128;

    for (int i = tid; i < 64 * 64 / 4; i += 256)
        ((float4*)W)[i] = ((const float4*)Wn)[i];
    if (tid < 64) { s_bn[tid] = bn[tid]; s_wg[tid] = Wg[tid]; }
    if (tid == 0) s_bg = bg[0];

    // gather (contiguous rows)
    {
        int r = tid >> 4;       // 0..15
        int c = tid & 15;
        for (int rr = r; rr < 128; rr += 16) {
            int n = n0 + rr;
            float4 v = (n < N) ? ((const float4*)(g_hneigh + (size_t)n * DIM))[c]
                               : make_float4(0.f, 0.f, 0.f, 0.f);
            ((float4*)(A + rr * 64))[c] = v;
        }
    }
    __syncthreads();

    const int tc = tid & 15;
    const int tr = tid >> 4;
    const float* Abase = A + tr * 8 * 64;

    float acc[8][4];
    {
        float b0 = s_bn[tc * 4 + 0], b1v = s_bn[tc * 4 + 1];
        float b2v = s_bn[tc * 4 + 2], b3 = s_bn[tc * 4 + 3];
        #pragma unroll
        for (int i = 0; i < 8; i++) {
            acc[i][0] = b0; acc[i][1] = b1v; acc[i][2] = b2v; acc[i][3] = b3;
        }
    }
    #pragma unroll 4
    for (int k = 0; k < 64; k++) {
        float4 wv = *(const float4*)(W + k * 64 + tc * 4);
        float a[8];
        #pragma unroll
        for (int i = 0; i < 8; i++) a[i] = Abase[i * 64 + k];
        #pragma unroll
        for (int i = 0; i < 8; i++) {
            acc[i][0] = fmaf(a[i], wv.x, acc[i][0]);
            acc[i][1] = fmaf(a[i], wv.y, acc[i][1]);
            acc[i][2] = fmaf(a[i], wv.z, acc[i][2]);
            acc[i][3] = fmaf(a[i], wv.w, acc[i][3]);
        }
    }
    #pragma unroll
    for (int i = 0; i < 8; i++) {
        int r = tr * 8 + i;
        int n = n0 + r;
        float4 hv;
        hv.x = fmaxf(acc[i][0], 0.f); hv.y = fmaxf(acc[i][1], 0.f);
        hv.z = fmaxf(acc[i][2], 0.f); hv.w = fmaxf(acc[i][3], 0.f);
        *(float4*)(H + r * 64 + tc * 4) = hv;
        if (n < N) *(float4*)(g_h2 + (size_t)n * DIM + tc * 4) = hv;
    }
    __syncthreads();

    // gate (rotated index -> conflict-free)
    if (tid < 128) {
        int n = n0 + tid;
        if (n < N) {
            const float* hr = H + tid * 64;
            float gacc = s_bg;
            #pragma unroll
            for (int j = 0; j < 64; j++) {
                int jj = (j + tid) & 63;
                gacc = fmaf(hr[jj], s_wg[jj], gacc);
            }
            g_gate[n] = gacc;
        }
    }
}

// ---------------------------------------------------------------------------
// Pool kernel: one block per graph (graph_ids sorted).
// segment max -> exp-weighted sums -> classifier
// ---------------------------------------------------------------------------
__global__ __launch_bounds__(256) void pool_kernel(
    const int* __restrict__ gid,
    const float* __restrict__ Wfc, const float* __restrict__ bfc,
    float* __restrict__ out, int N, int C)
{
    const int g   = blockIdx.x;
    const int tid = threadIdx.x;
    const int lane = tid & 31;
    const int w    = tid >> 5;

    // lower_bound for g and g+1
    int start, end;
    {
        int lo = 0, hi = N;
        while (lo < hi) { int mid = (lo + hi) >> 1; if (gid[mid] < g) lo = mid + 1; else hi = mid; }
        start = lo;
        lo = start; hi = N;
        while (lo < hi) { int mid = (lo + hi) >> 1; if (gid[mid] < g + 1) lo = mid + 1; else hi = mid; }
        end = lo;
    }

    __shared__ float s_red[8 * 64];
    __shared__ float s_scalar[8];
    __shared__ float s_gmax;
    __shared__ float s_pool[64];
    __shared__ float s_denom;

    // pass 1: segment max of gate
    float lmax = -3.4e38f;
    for (int n = start + tid; n < end; n += 256) lmax = fmaxf(lmax, g_gate[n]);
    #pragma unroll
    for (int o = 16; o > 0; o >>= 1) lmax = fmaxf(lmax, __shfl_xor_sync(0xFFFFFFFFu, lmax, o));
    if (lane == 0) s_scalar[w] = lmax;
    __syncthreads();
    if (tid == 0) {
        float m = s_scalar[0];
        #pragma unroll
        for (int i = 1; i < 8; i++) m = fmaxf(m, s_scalar[i]);
        s_gmax = m;
    }
    __syncthreads();
    const float gmax = s_gmax;

    // pass 2: denom + weighted feature sum (warp handles whole rows)
    float p0 = 0.f, p1 = 0.f, ds = 0.f;
    for (int n = start + w; n < end; n += 8) {
        float a = __expf(g_gate[n] - gmax);
        const float* hr = g_h2 + (size_t)n * DIM;
        p0 = fmaf(a, hr[lane],      p0);
        p1 = fmaf(a, hr[lane + 32], p1);
        ds += a;
    }
    s_red[w * 64 + lane]      = p0;
    s_red[w * 64 + lane + 32] = p1;
    if (lane == 0) s_scalar[w] = ds;
    __syncthreads();
    if (tid < 64) {
        float s = 0.f;
        #pragma unroll
        for (int i = 0; i < 8; i++) s += s_red[i * 64 + tid];
        s_pool[tid] = s;
    }
    if (tid == 0) {
        float d = 0.f;
        #pragma unroll
        for (int i = 0; i < 8; i++) d += s_scalar[i];
        s_denom = d;
    }
    __syncthreads();

    // classifier: out[g][c] = (pooled/denom) @ Wfc + bfc
    if (tid < C) {
        float o;
        if (end > start) {
            float inv = 1.0f / s_denom;
            float acc = 0.f;
            for (int j = 0; j < 64; j++)
                acc = fmaf(s_pool[j], Wfc[j * C + tid], acc);
            o = fmaf(acc, inv, bfc[tid]);
        } else {
            o = bfc[tid];
        }
        out[g * C + tid] = o;
    }
}

// ---------------------------------------------------------------------------
// launch
// ---------------------------------------------------------------------------
extern "C" void kernel_launch(void* const* d_in, const int* in_sizes, int n_in,
                              void* d_out, int out_size) {
    const float* x   = (const float*)d_in[0];
    const float* We1 = (const float*)d_in[1];
    const float* be1 = (const float*)d_in[2];
    const float* We2 = (const float*)d_in[3];
    const float* be2 = (const float*)d_in[4];
    const float* Wn  = (const float*)d_in[5];
    const float* bn  = (const float*)d_in[6];
    const float* Wg  = (const float*)d_in[7];
    const float* bg  = (const float*)d_in[8];
    const float* Wfc = (const float*)d_in[9];
    const float* bfc = (const float*)d_in[10];
    const int*   src = (const int*)d_in[11];
    const int*   dst = (const int*)d_in[12];
    const int*   gid = (const int*)d_in[13];
    float* out = (float*)d_out;

    const int N = in_sizes[0] / DIM;
    const int E = in_sizes[11];
    const int C = in_sizes[9] / DIM;   // 10
    const int G = out_size / C;        // 128

    const int SMEM_EDGE = (128 * 128 + 128 * 64 + 64 * 64 + 128 * 64) * 4;  // 144 KB
    const int SMEM_NODE = (128 * 64 + 64 * 64 + 128 * 64) * 4;              // 80 KB
    cudaFuncSetAttribute(edge_kernel, cudaFuncAttributeMaxDynamicSharedMemorySize, SMEM_EDGE);
    cudaFuncSetAttribute(node_kernel, cudaFuncAttributeMaxDynamicSharedMemorySize, SMEM_NODE);

    int n4 = N * DIM / 4;
    zero_kernel<<<(n4 + 255) / 256, 256>>>(n4);

    edge_kernel<<<(E + 127) / 128, 256, SMEM_EDGE>>>(x, We1, be1, We2, be2, src, dst, E);

    node_kernel<<<(N + 127) / 128, 256, SMEM_NODE>>>(Wn, bn, Wg, bg, N);

    pool_kernel<<<G, 256>>>(gid, Wfc, bfc, out, N, C);
}